// round 1
// baseline (speedup 1.0000x reference)
#include <cuda_runtime.h>
#include <math.h>

#define DMODEL 1024
#define DINNER 2048
#define DSTATE 16
#define DCONV  4
#define DTRANK 64
#define BATCH  4
#define SEQ    2048
#define MTOK   (BATCH*SEQ)           // 8192 tokens
#define XPROJ_N (DTRANK + 2*DSTATE)  // 96

// ---------------- scratch (static device globals; no allocation) -------------
static __device__ float g_xr  [(size_t)MTOK * 2 * DINNER]; // in_proj out (B,L,4096)
static __device__ float g_u   [(size_t)MTOK * DINNER];     // conv+silu  (B,L,D)
static __device__ float g_uT  [(size_t)MTOK * DINNER];     // (B,D,L)
static __device__ float g_dt  [(size_t)MTOK * DINNER];     // softplus(dt) (B,L,D)
static __device__ float g_dtT [(size_t)MTOK * DINNER];     // (B,D,L)
static __device__ float g_xdbl[(size_t)MTOK * XPROJ_N];    // (B*L,96)
static __device__ float g_Bt  [(size_t)BATCH * DSTATE * SEQ]; // (B,16,L)
static __device__ float g_Ct  [(size_t)BATCH * DSTATE * SEQ];
static __device__ float g_yT  [(size_t)MTOK * DINNER];     // scan out (B,D,L)
static __device__ float g_yg  [(size_t)MTOK * DINNER];     // gated (B,L,D)

// ---------------- generic NT SGEMM: C[M,N] = A[M,K] * B[N,K]^T ---------------
// EPI: 0 = none, 1 = softplus(v + bias[n])
template<int BM,int BN,int BK,int TM,int TN,int EPI>
__global__ void __launch_bounds__((BM/TM)*(BN/TN))
sgemm_nt(int M,int N,int K,
         const float* __restrict__ A, int lda,
         const float* __restrict__ B, int ldb,
         float* __restrict__ C, int ldc,
         const float* __restrict__ bias)
{
    constexpr int NT = (BM/TM)*(BN/TN);
    constexpr int KV = BK/4;
    constexpr int LA = (BM*BK)/(4*NT);
    constexpr int LB = (BN*BK)/(4*NT);
    static_assert(LA >= 1 && LB >= 1, "tile/thread mismatch");

    __shared__ float As[BK][BM];
    __shared__ float Bs[BK][BN];

    const int tid = threadIdx.x;
    const int m0  = blockIdx.y * BM;
    const int n0  = blockIdx.x * BN;
    const float* Ap = A + (size_t)m0 * lda;
    const float* Bp = B + (size_t)n0 * ldb;

    const int ncol = BN/TN;
    const int trow = tid / ncol;
    const int tcol = tid % ncol;

    float acc[TM][TN];
    #pragma unroll
    for (int i=0;i<TM;++i)
        #pragma unroll
        for (int j=0;j<TN;++j) acc[i][j]=0.f;

    for (int k0 = 0; k0 < K; k0 += BK) {
        #pragma unroll
        for (int i = 0; i < LA; ++i) {
            int f   = tid + i*NT;
            int row = f / KV, c4 = f % KV;
            float4 v = *(const float4*)(Ap + (size_t)row*lda + k0 + c4*4);
            As[c4*4+0][row]=v.x; As[c4*4+1][row]=v.y;
            As[c4*4+2][row]=v.z; As[c4*4+3][row]=v.w;
        }
        #pragma unroll
        for (int i = 0; i < LB; ++i) {
            int f   = tid + i*NT;
            int row = f / KV, c4 = f % KV;
            float4 v = *(const float4*)(Bp + (size_t)row*ldb + k0 + c4*4);
            Bs[c4*4+0][row]=v.x; Bs[c4*4+1][row]=v.y;
            Bs[c4*4+2][row]=v.z; Bs[c4*4+3][row]=v.w;
        }
        __syncthreads();
        #pragma unroll
        for (int kk = 0; kk < BK; ++kk) {
            float a[TM], bb[TN];
            #pragma unroll
            for (int i=0;i<TM;++i) a[i]  = As[kk][trow*TM+i];
            #pragma unroll
            for (int j=0;j<TN;++j) bb[j] = Bs[kk][tcol*TN+j];
            #pragma unroll
            for (int i=0;i<TM;++i)
                #pragma unroll
                for (int j=0;j<TN;++j)
                    acc[i][j] = fmaf(a[i], bb[j], acc[i][j]);
        }
        __syncthreads();
    }

    #pragma unroll
    for (int i=0;i<TM;++i) {
        int m = m0 + trow*TM + i;
        float* Crow = C + (size_t)m*ldc + n0 + tcol*TN;
        #pragma unroll
        for (int j=0;j<TN;j+=4) {
            float4 v;
            float t0=acc[i][j+0], t1=acc[i][j+1], t2=acc[i][j+2], t3=acc[i][j+3];
            if (EPI == 1) {
                int nb = n0 + tcol*TN + j;
                t0 += bias[nb+0]; t1 += bias[nb+1]; t2 += bias[nb+2]; t3 += bias[nb+3];
                t0 = fmaxf(t0,0.f)+log1pf(expf(-fabsf(t0)));
                t1 = fmaxf(t1,0.f)+log1pf(expf(-fabsf(t1)));
                t2 = fmaxf(t2,0.f)+log1pf(expf(-fabsf(t2)));
                t3 = fmaxf(t3,0.f)+log1pf(expf(-fabsf(t3)));
            }
            v.x=t0; v.y=t1; v.z=t2; v.w=t3;
            *(float4*)(Crow + j) = v;
        }
    }
}

// ------------- small-N GEMM for x_proj: (8192 x 96) = U(8192x2048) W(96x2048)^T
__global__ void __launch_bounds__(256)
sgemm_xproj(const float* __restrict__ A, const float* __restrict__ W,
            float* __restrict__ C)
{
    // BM=32, BN=96, BK=8, TM=2, TN=6, 256 threads, 256 blocks
    __shared__ float As[8][32];
    __shared__ float Bs[8][96];
    const int tid = threadIdx.x;
    const int m0  = blockIdx.x * 32;
    const int trow = tid / 16;
    const int tcol = tid % 16;
    float acc[2][6];
    #pragma unroll
    for (int i=0;i<2;++i)
        #pragma unroll
        for (int j=0;j<6;++j) acc[i][j]=0.f;

    for (int k0 = 0; k0 < DINNER; k0 += 8) {
        { int row = tid/8, col = tid%8;
          As[col][row] = A[(size_t)(m0+row)*DINNER + k0 + col]; }
        #pragma unroll
        for (int i=0;i<3;++i) {
            int f = tid + i*256;
            int row = f/8, col = f%8;
            Bs[col][row] = W[(size_t)row*DINNER + k0 + col];
        }
        __syncthreads();
        #pragma unroll
        for (int kk=0;kk<8;++kk) {
            float a0 = As[kk][trow*2+0];
            float a1 = As[kk][trow*2+1];
            #pragma unroll
            for (int j=0;j<6;++j) {
                float b = Bs[kk][tcol*6+j];
                acc[0][j] = fmaf(a0,b,acc[0][j]);
                acc[1][j] = fmaf(a1,b,acc[1][j]);
            }
        }
        __syncthreads();
    }
    #pragma unroll
    for (int i=0;i<2;++i)
        #pragma unroll
        for (int j=0;j<6;++j)
            C[(size_t)(m0+trow*2+i)*XPROJ_N + tcol*6 + j] = acc[i][j];
}

// ------------- causal depthwise conv1d + SiLU --------------------------------
__global__ void __launch_bounds__(256)
conv_silu(const float* __restrict__ xr, const float* __restrict__ w,
          const float* __restrict__ bias, float* __restrict__ u)
{
    size_t n = (size_t)blockIdx.x * 256 + threadIdx.x;   // over B*L*DINNER
    int d  = (int)(n % DINNER);
    size_t bt = n / DINNER;
    int t  = (int)(bt % SEQ);
    int b  = (int)(bt / SEQ);
    float4 wv = *(const float4*)(w + (size_t)d*4);
    const float* col = xr + (size_t)b * SEQ * (2*DINNER) + d; // xs part, row stride 4096
    float acc = bias[d];
    if (t-3 >= 0) acc = fmaf(wv.x, col[(size_t)(t-3)*(2*DINNER)], acc);
    if (t-2 >= 0) acc = fmaf(wv.y, col[(size_t)(t-2)*(2*DINNER)], acc);
    if (t-1 >= 0) acc = fmaf(wv.z, col[(size_t)(t-1)*(2*DINNER)], acc);
    acc = fmaf(wv.w, col[(size_t)t*(2*DINNER)], acc);
    u[n] = acc / (1.f + expf(-acc));   // SiLU
}

// ------------- 2048x2048 per-batch transpose (B,L,D) -> (B,D,L) --------------
__global__ void __launch_bounds__(256)
transpose_bt(const float* __restrict__ in, float* __restrict__ out)
{
    __shared__ float tile[32][33];
    const int b = blockIdx.z;
    const float* inb = in  + (size_t)b*SEQ*DINNER;
    float*      outb = out + (size_t)b*SEQ*DINNER;
    int x  = blockIdx.x*32 + threadIdx.x;   // d
    int y0 = blockIdx.y*32;                 // t
    #pragma unroll
    for (int j=0;j<4;++j)
        tile[threadIdx.y + j*8][threadIdx.x] =
            inb[(size_t)(y0 + threadIdx.y + j*8)*DINNER + x];
    __syncthreads();
    int xo  = blockIdx.y*32 + threadIdx.x;  // t
    int yo0 = blockIdx.x*32;                // d
    #pragma unroll
    for (int j=0;j<4;++j)
        outb[(size_t)(yo0 + threadIdx.y + j*8)*SEQ + xo] =
            tile[threadIdx.x][threadIdx.y + j*8];
}

// ------------- split x_dbl cols into Bt/Ct (B,16,L) ---------------------------
__global__ void __launch_bounds__(256)
split_bc(const float* __restrict__ xdbl, float* __restrict__ Bt, float* __restrict__ Ct)
{
    int idx = blockIdx.x*256 + threadIdx.x;     // B*L*16 = 131072
    if (idx >= BATCH*SEQ*DSTATE) return;
    int s  = idx & 15;
    int bt = idx >> 4;
    int t  = bt % SEQ;
    int b  = bt / SEQ;
    const float* row = xdbl + (size_t)bt * XPROJ_N;
    Bt[((size_t)b*DSTATE + s)*SEQ + t] = row[DTRANK + s];
    Ct[((size_t)b*DSTATE + s)*SEQ + t] = row[DTRANK + DSTATE + s];
}

// ------------- selective scan: 16 lanes per channel, 1 state per lane --------
__global__ void __launch_bounds__(256)
scan_kernel(const float* __restrict__ uT, const float* __restrict__ dtT,
            const float* __restrict__ Bt, const float* __restrict__ Ct,
            const float* __restrict__ A_log, const float* __restrict__ Dp,
            float* __restrict__ yT)
{
    const int tid = threadIdx.x;
    const int grp = tid >> 4;            // channel within block (0..15)
    const int s   = tid & 15;            // state
    const int c   = blockIdx.x*16 + grp; // global channel in [0, B*DINNER)
    const int b   = c >> 11;             // /2048
    const int d   = c & (DINNER-1);

    const float LOG2E = 1.4426950408889634f;
    const float Aval  = -expf(A_log[(size_t)d*DSTATE + s]) * LOG2E;
    const float Dd    = Dp[d];

    const float4* u4  = (const float4*)(uT  + (size_t)c*SEQ);
    const float4* dt4 = (const float4*)(dtT + (size_t)c*SEQ);
    const float4* B4  = (const float4*)(Bt  + ((size_t)b*DSTATE + s)*SEQ);
    const float4* C4  = (const float4*)(Ct  + ((size_t)b*DSTATE + s)*SEQ);
    float4*       y4  = (float4*)(yT + (size_t)c*SEQ);

    float h = 0.f;
    #pragma unroll 1
    for (int i = 0; i < SEQ/4; ++i) {
        float4 uu = u4[i];   // broadcast across the 16-lane group
        float4 dd = dt4[i];
        float4 bb = B4[i];   // per-lane state series
        float4 cc = C4[i];
        float4 yo;

        #define SCAN_STEP(UJ, DJ, BJ, CJ, YJ) {                       \
            float dA = exp2f((DJ) * Aval);                            \
            h = fmaf(dA, h, (DJ)*(UJ)*(BJ));                          \
            float yp = h * (CJ);                                      \
            yp += __shfl_xor_sync(0xffffffffu, yp, 8);                \
            yp += __shfl_xor_sync(0xffffffffu, yp, 4);                \
            yp += __shfl_xor_sync(0xffffffffu, yp, 2);                \
            yp += __shfl_xor_sync(0xffffffffu, yp, 1);                \
            YJ = fmaf(Dd, (UJ), yp); }

        SCAN_STEP(uu.x, dd.x, bb.x, cc.x, yo.x)
        SCAN_STEP(uu.y, dd.y, bb.y, cc.y, yo.y)
        SCAN_STEP(uu.z, dd.z, bb.z, cc.z, yo.z)
        SCAN_STEP(uu.w, dd.w, bb.w, cc.w, yo.w)
        #undef SCAN_STEP

        if (s == 0) y4[i] = yo;
    }
}

// ------------- gate: yg(B,L,D) = yT(B,D,L)^T * silu(res) ----------------------
__global__ void __launch_bounds__(256)
gate_transpose(const float* __restrict__ yT, const float* __restrict__ xr,
               float* __restrict__ yg)
{
    __shared__ float tile[32][33];
    const int b = blockIdx.z;
    const float* yTb = yT + (size_t)b*DINNER*SEQ;
    int t  = blockIdx.x*32 + threadIdx.x;
    int d0 = blockIdx.y*32;
    #pragma unroll
    for (int j=0;j<4;++j)
        tile[threadIdx.y + j*8][threadIdx.x] =
            yTb[(size_t)(d0 + threadIdx.y + j*8)*SEQ + t];
    __syncthreads();
    int d  = blockIdx.y*32 + threadIdx.x;
    int t0 = blockIdx.x*32;
    #pragma unroll
    for (int j=0;j<4;++j) {
        int tt = t0 + threadIdx.y + j*8;
        float r = xr[((size_t)(b*SEQ + tt))*(2*DINNER) + DINNER + d];
        float sil = r / (1.f + expf(-r));
        yg[((size_t)(b*SEQ + tt))*DINNER + d] =
            tile[threadIdx.x][threadIdx.y + j*8] * sil;
    }
}

// ------------------------------- launch --------------------------------------
extern "C" void kernel_launch(void* const* d_in, const int* in_sizes, int n_in,
                              void* d_out, int out_size)
{
    const float* x         = (const float*)d_in[0];
    const float* in_proj_w = (const float*)d_in[1];
    const float* conv_w    = (const float*)d_in[2];
    const float* conv_b    = (const float*)d_in[3];
    const float* x_proj_w  = (const float*)d_in[4];
    const float* dt_proj_w = (const float*)d_in[5];
    const float* dt_proj_b = (const float*)d_in[6];
    const float* A_log     = (const float*)d_in[7];
    const float* Dvec      = (const float*)d_in[8];
    const float* out_proj_w= (const float*)d_in[9];
    float* out             = (float*)d_out;

    float *xr, *u, *uT, *dt, *dtT, *xdbl, *Btp, *Ctp, *yT, *yg;
    cudaGetSymbolAddress((void**)&xr,   g_xr);
    cudaGetSymbolAddress((void**)&u,    g_u);
    cudaGetSymbolAddress((void**)&uT,   g_uT);
    cudaGetSymbolAddress((void**)&dt,   g_dt);
    cudaGetSymbolAddress((void**)&dtT,  g_dtT);
    cudaGetSymbolAddress((void**)&xdbl, g_xdbl);
    cudaGetSymbolAddress((void**)&Btp,  g_Bt);
    cudaGetSymbolAddress((void**)&Ctp,  g_Ct);
    cudaGetSymbolAddress((void**)&yT,   g_yT);
    cudaGetSymbolAddress((void**)&yg,   g_yg);

    // 1) in_proj: xr[8192,4096] = x[8192,1024] @ in_proj_w^T
    sgemm_nt<128,128,8,8,8,0><<<dim3(2*DINNER/128, MTOK/128), 256>>>(
        MTOK, 2*DINNER, DMODEL, x, DMODEL, in_proj_w, DMODEL, xr, 2*DINNER, nullptr);

    // 2) causal depthwise conv + SiLU -> u (B,L,D)
    conv_silu<<<(MTOK*DINNER)/256, 256>>>(xr, conv_w, conv_b, u);

    // 3) u -> uT (B,D,L)
    transpose_bt<<<dim3(DINNER/32, SEQ/32, BATCH), dim3(32,8)>>>(u, uT);

    // 4) x_dbl[8192,96] = u @ x_proj_w^T
    sgemm_xproj<<<MTOK/32, 256>>>(u, x_proj_w, xdbl);

    // 5) dt[8192,2048] = softplus(x_dbl[:, :64] @ dt_proj_w^T + b)
    sgemm_nt<128,128,8,8,8,1><<<dim3(DINNER/128, MTOK/128), 256>>>(
        MTOK, DINNER, DTRANK, xdbl, XPROJ_N, dt_proj_w, DTRANK, dt, DINNER, dt_proj_b);

    // 6) dt -> dtT (B,D,L)
    transpose_bt<<<dim3(DINNER/32, SEQ/32, BATCH), dim3(32,8)>>>(dt, dtT);

    // 7) split B/C columns -> (B,16,L)
    split_bc<<<(BATCH*SEQ*DSTATE)/256, 256>>>(xdbl, Btp, Ctp);

    // 8) selective scan -> yT (B,D,L)
    scan_kernel<<<(BATCH*DINNER)/16, 256>>>(uT, dtT, Btp, Ctp, A_log, Dvec, yT);

    // 9) gate with silu(res), transpose back -> yg (B,L,D)
    gate_transpose<<<dim3(SEQ/32, DINNER/32, BATCH), dim3(32,8)>>>(yT, xr, yg);

    // 10) out_proj: out[8192,1024] = yg @ out_proj_w^T
    sgemm_nt<128,128,8,8,8,0><<<dim3(DMODEL/128, MTOK/128), 256>>>(
        MTOK, DMODEL, DINNER, yg, DINNER, out_proj_w, DINNER, out, DMODEL, nullptr);
}

// round 2
// speedup vs baseline: 2.1881x; 2.1881x over previous
#include <cuda_runtime.h>
#include <math.h>
#include <stdint.h>

#define DMODEL 1024
#define DINNER 2048
#define DSTATE 16
#define DTRANK 64
#define BATCH  4
#define SEQ    2048
#define MTOK   (BATCH*SEQ)           // 8192 tokens
#define XPN    128                   // padded x_proj N (real 96)

// ---------------- scratch (static device globals; no allocation) -------------
static __device__ float g_xr  [(size_t)MTOK * 2 * DINNER]; // in_proj out (B,L,4096)
static __device__ float g_u   [(size_t)MTOK * DINNER];     // conv+silu  (B,L,D)
static __device__ float g_uT  [(size_t)MTOK * DINNER];     // (B,D,L)
static __device__ float g_dt  [(size_t)MTOK * DINNER];     // softplus(dt) (B,L,D)
static __device__ float g_dtT [(size_t)MTOK * DINNER];     // (B,D,L)
static __device__ float g_xdbl[(size_t)MTOK * XPN];        // (B*L,128) padded
static __device__ float g_wpad[(size_t)XPN * DINNER];      // padded x_proj_w (128,2048)
static __device__ float g_Bt  [(size_t)BATCH * DSTATE * SEQ]; // (B,16,L)
static __device__ float g_Ct  [(size_t)BATCH * DSTATE * SEQ];
static __device__ float g_yT  [(size_t)MTOK * DINNER];     // scan out (B,D,L)
static __device__ float g_yg  [(size_t)MTOK * DINNER];     // gated (B,L,D)

// --------------------------- tf32 helpers ------------------------------------
__device__ __forceinline__ float f2tf32(float x) {
    uint32_t r;
    asm("cvt.rna.tf32.f32 %0, %1;" : "=r"(r) : "f"(x));
    return __uint_as_float(r);
}

__device__ __forceinline__ void mma_tf32(float* c, const uint32_t* a, const uint32_t* b) {
    asm volatile(
        "mma.sync.aligned.m16n8k8.row.col.f32.tf32.tf32.f32 "
        "{%0,%1,%2,%3}, {%4,%5,%6,%7}, {%8,%9}, {%0,%1,%2,%3};"
        : "+f"(c[0]), "+f"(c[1]), "+f"(c[2]), "+f"(c[3])
        : "r"(a[0]), "r"(a[1]), "r"(a[2]), "r"(a[3]), "r"(b[0]), "r"(b[1]));
}

__device__ __forceinline__ float softplusf(float x) {
    return fmaxf(x, 0.f) + log1pf(expf(-fabsf(x)));
}

// -------------- TF32 tensor-core NT GEMM: C[M,N] = A[M,K] * B[N,K]^T ---------
// BM=BN=128, BK=32. 256 threads = 8 warps as 2(m) x 4(n), warp tile 64x32.
// EPI: 0 = none, 1 = softplus(v + bias[n])
template<int EPI>
__global__ void __launch_bounds__(256, 2)
mma_nt(int M, int N, int K,
       const float* __restrict__ A, int lda,
       const float* __restrict__ B, int ldb,
       float* __restrict__ C, int ldc,
       const float* __restrict__ bias)
{
    constexpr int BM = 128, BN = 128, BK = 32, LDS = BK + 4; // 36: frag loads conflict-free
    __shared__ float As[BM][LDS];
    __shared__ float Bs[BN][LDS];

    const int tid  = threadIdx.x;
    const int wid  = tid >> 5;
    const int lane = tid & 31;
    const int gid  = lane >> 2;      // 0..7
    const int tig  = lane & 3;       // 0..3
    const int wm   = (wid >> 2) * 64;  // {0,64}
    const int wn   = (wid & 3) * 32;   // {0,32,64,96}

    const int m0 = blockIdx.y * BM;
    const int n0 = blockIdx.x * BN;
    const float* Ap = A + (size_t)m0 * lda;
    const float* Bp = B + (size_t)n0 * ldb;

    const int lrow = tid >> 3;          // 0..31
    const int lc4  = (tid & 7) * 4;     // 0..28

    float acc[4][4][4];
    #pragma unroll
    for (int i = 0; i < 4; ++i)
        #pragma unroll
        for (int j = 0; j < 4; ++j)
            #pragma unroll
            for (int q = 0; q < 4; ++q) acc[i][j][q] = 0.f;

    for (int k0 = 0; k0 < K; k0 += BK) {
        #pragma unroll
        for (int i = 0; i < 4; ++i) {
            float4 v = *(const float4*)(Ap + (size_t)(lrow + 32*i)*lda + k0 + lc4);
            float4 w; w.x = f2tf32(v.x); w.y = f2tf32(v.y); w.z = f2tf32(v.z); w.w = f2tf32(v.w);
            *(float4*)&As[lrow + 32*i][lc4] = w;
        }
        #pragma unroll
        for (int i = 0; i < 4; ++i) {
            float4 v = *(const float4*)(Bp + (size_t)(lrow + 32*i)*ldb + k0 + lc4);
            float4 w; w.x = f2tf32(v.x); w.y = f2tf32(v.y); w.z = f2tf32(v.z); w.w = f2tf32(v.w);
            *(float4*)&Bs[lrow + 32*i][lc4] = w;
        }
        __syncthreads();

        #pragma unroll
        for (int ks = 0; ks < BK; ks += 8) {
            uint32_t af[4][4], bf[4][2];
            #pragma unroll
            for (int im = 0; im < 4; ++im) {
                int mr = wm + im*16 + gid;
                af[im][0] = __float_as_uint(As[mr    ][ks + tig    ]);
                af[im][1] = __float_as_uint(As[mr + 8][ks + tig    ]);
                af[im][2] = __float_as_uint(As[mr    ][ks + tig + 4]);
                af[im][3] = __float_as_uint(As[mr + 8][ks + tig + 4]);
            }
            #pragma unroll
            for (int in = 0; in < 4; ++in) {
                int nr = wn + in*8 + gid;
                bf[in][0] = __float_as_uint(Bs[nr][ks + tig    ]);
                bf[in][1] = __float_as_uint(Bs[nr][ks + tig + 4]);
            }
            #pragma unroll
            for (int im = 0; im < 4; ++im)
                #pragma unroll
                for (int in = 0; in < 4; ++in)
                    mma_tf32(acc[im][in], af[im], bf[in]);
        }
        __syncthreads();
    }

    // epilogue: c0,c1 -> (m, n..n+1); c2,c3 -> (m+8, n..n+1)
    #pragma unroll
    for (int im = 0; im < 4; ++im) {
        #pragma unroll
        for (int in = 0; in < 4; ++in) {
            int m = m0 + wm + im*16 + gid;
            int n = n0 + wn + in*8 + tig*2;
            float t0 = acc[im][in][0], t1 = acc[im][in][1];
            float t2 = acc[im][in][2], t3 = acc[im][in][3];
            if (EPI == 1) {
                float b0 = bias[n], b1 = bias[n+1];
                t0 = softplusf(t0 + b0); t1 = softplusf(t1 + b1);
                t2 = softplusf(t2 + b0); t3 = softplusf(t3 + b1);
            }
            float2 v0; v0.x = t0; v0.y = t1;
            float2 v1; v1.x = t2; v1.y = t3;
            *(float2*)(C + (size_t)m*ldc + n)       = v0;
            *(float2*)(C + (size_t)(m+8)*ldc + n)   = v1;
        }
    }
}

// ------------- pad x_proj_w (96,2048) -> (128,2048) zero-padded ---------------
__global__ void __launch_bounds__(256)
pad_w(const float* __restrict__ w, float* __restrict__ wp)
{
    int idx = blockIdx.x * 256 + threadIdx.x;      // over 128*2048
    if (idx >= XPN * DINNER) return;
    int n = idx / DINNER;
    wp[idx] = (n < DTRANK + 2*DSTATE) ? w[idx] : 0.f;
}

// ------------- causal depthwise conv1d + SiLU --------------------------------
__global__ void __launch_bounds__(256)
conv_silu(const float* __restrict__ xr, const float* __restrict__ w,
          const float* __restrict__ bias, float* __restrict__ u)
{
    size_t n = (size_t)blockIdx.x * 256 + threadIdx.x;   // over B*L*DINNER
    int d  = (int)(n % DINNER);
    size_t bt = n / DINNER;
    int t  = (int)(bt % SEQ);
    int b  = (int)(bt / SEQ);
    float4 wv = *(const float4*)(w + (size_t)d*4);
    const float* col = xr + (size_t)b * SEQ * (2*DINNER) + d;
    float acc = bias[d];
    if (t-3 >= 0) acc = fmaf(wv.x, col[(size_t)(t-3)*(2*DINNER)], acc);
    if (t-2 >= 0) acc = fmaf(wv.y, col[(size_t)(t-2)*(2*DINNER)], acc);
    if (t-1 >= 0) acc = fmaf(wv.z, col[(size_t)(t-1)*(2*DINNER)], acc);
    acc = fmaf(wv.w, col[(size_t)t*(2*DINNER)], acc);
    u[n] = acc / (1.f + expf(-acc));   // SiLU
}

// ------------- 2048x2048 per-batch transpose (B,L,D) -> (B,D,L) --------------
__global__ void __launch_bounds__(256)
transpose_bt(const float* __restrict__ in, float* __restrict__ out)
{
    __shared__ float tile[32][33];
    const int b = blockIdx.z;
    const float* inb = in  + (size_t)b*SEQ*DINNER;
    float*      outb = out + (size_t)b*SEQ*DINNER;
    int x  = blockIdx.x*32 + threadIdx.x;
    int y0 = blockIdx.y*32;
    #pragma unroll
    for (int j=0;j<4;++j)
        tile[threadIdx.y + j*8][threadIdx.x] =
            inb[(size_t)(y0 + threadIdx.y + j*8)*DINNER + x];
    __syncthreads();
    int xo  = blockIdx.y*32 + threadIdx.x;
    int yo0 = blockIdx.x*32;
    #pragma unroll
    for (int j=0;j<4;++j)
        outb[(size_t)(yo0 + threadIdx.y + j*8)*SEQ + xo] =
            tile[threadIdx.x][threadIdx.y + j*8];
}

// ------------- split x_dbl cols into Bt/Ct (B,16,L) ---------------------------
__global__ void __launch_bounds__(256)
split_bc(const float* __restrict__ xdbl, float* __restrict__ Bt, float* __restrict__ Ct)
{
    int idx = blockIdx.x*256 + threadIdx.x;     // B*L*16
    if (idx >= BATCH*SEQ*DSTATE) return;
    int s  = idx & 15;
    int bt = idx >> 4;
    int t  = bt % SEQ;
    int b  = bt / SEQ;
    const float* row = xdbl + (size_t)bt * XPN;
    Bt[((size_t)b*DSTATE + s)*SEQ + t] = row[DTRANK + s];
    Ct[((size_t)b*DSTATE + s)*SEQ + t] = row[DTRANK + DSTATE + s];
}

// ------------- selective scan: 16 lanes per channel, 1 state per lane --------
__global__ void __launch_bounds__(256)
scan_kernel(const float* __restrict__ uT, const float* __restrict__ dtT,
            const float* __restrict__ Bt, const float* __restrict__ Ct,
            const float* __restrict__ A_log, const float* __restrict__ Dp,
            float* __restrict__ yT)
{
    const int tid = threadIdx.x;
    const int grp = tid >> 4;
    const int s   = tid & 15;
    const int c   = blockIdx.x*16 + grp;
    const int b   = c >> 11;
    const int d   = c & (DINNER-1);

    const float LOG2E = 1.4426950408889634f;
    const float Aval  = -expf(A_log[(size_t)d*DSTATE + s]) * LOG2E;
    const float Dd    = Dp[d];

    const float4* u4  = (const float4*)(uT  + (size_t)c*SEQ);
    const float4* dt4 = (const float4*)(dtT + (size_t)c*SEQ);
    const float4* B4  = (const float4*)(Bt  + ((size_t)b*DSTATE + s)*SEQ);
    const float4* C4  = (const float4*)(Ct  + ((size_t)b*DSTATE + s)*SEQ);
    float4*       y4  = (float4*)(yT + (size_t)c*SEQ);

    float h = 0.f;
    #pragma unroll 1
    for (int i = 0; i < SEQ/4; ++i) {
        float4 uu = u4[i];
        float4 dd = dt4[i];
        float4 bb = B4[i];
        float4 cc = C4[i];
        float4 yo;

        #define SCAN_STEP(UJ, DJ, BJ, CJ, YJ) {                       \
            float dA = exp2f((DJ) * Aval);                            \
            h = fmaf(dA, h, (DJ)*(UJ)*(BJ));                          \
            float yp = h * (CJ);                                      \
            yp += __shfl_xor_sync(0xffffffffu, yp, 8);                \
            yp += __shfl_xor_sync(0xffffffffu, yp, 4);                \
            yp += __shfl_xor_sync(0xffffffffu, yp, 2);                \
            yp += __shfl_xor_sync(0xffffffffu, yp, 1);                \
            YJ = fmaf(Dd, (UJ), yp); }

        SCAN_STEP(uu.x, dd.x, bb.x, cc.x, yo.x)
        SCAN_STEP(uu.y, dd.y, bb.y, cc.y, yo.y)
        SCAN_STEP(uu.z, dd.z, bb.z, cc.z, yo.z)
        SCAN_STEP(uu.w, dd.w, bb.w, cc.w, yo.w)
        #undef SCAN_STEP

        if (s == 0) y4[i] = yo;
    }
}

// ------------- gate: yg(B,L,D) = yT(B,D,L)^T * silu(res) ----------------------
__global__ void __launch_bounds__(256)
gate_transpose(const float* __restrict__ yT, const float* __restrict__ xr,
               float* __restrict__ yg)
{
    __shared__ float tile[32][33];
    const int b = blockIdx.z;
    const float* yTb = yT + (size_t)b*DINNER*SEQ;
    int t  = blockIdx.x*32 + threadIdx.x;
    int d0 = blockIdx.y*32;
    #pragma unroll
    for (int j=0;j<4;++j)
        tile[threadIdx.y + j*8][threadIdx.x] =
            yTb[(size_t)(d0 + threadIdx.y + j*8)*SEQ + t];
    __syncthreads();
    int d  = blockIdx.y*32 + threadIdx.x;
    int t0 = blockIdx.x*32;
    #pragma unroll
    for (int j=0;j<4;++j) {
        int tt = t0 + threadIdx.y + j*8;
        float r = xr[((size_t)(b*SEQ + tt))*(2*DINNER) + DINNER + d];
        float sil = r / (1.f + expf(-r));
        yg[((size_t)(b*SEQ + tt))*DINNER + d] =
            tile[threadIdx.x][threadIdx.y + j*8] * sil;
    }
}

// ------------------------------- launch --------------------------------------
extern "C" void kernel_launch(void* const* d_in, const int* in_sizes, int n_in,
                              void* d_out, int out_size)
{
    const float* x         = (const float*)d_in[0];
    const float* in_proj_w = (const float*)d_in[1];
    const float* conv_w    = (const float*)d_in[2];
    const float* conv_b    = (const float*)d_in[3];
    const float* x_proj_w  = (const float*)d_in[4];
    const float* dt_proj_w = (const float*)d_in[5];
    const float* dt_proj_b = (const float*)d_in[6];
    const float* A_log     = (const float*)d_in[7];
    const float* Dvec      = (const float*)d_in[8];
    const float* out_proj_w= (const float*)d_in[9];
    float* out             = (float*)d_out;

    float *xr, *u, *uT, *dt, *dtT, *xdbl, *wpad, *Btp, *Ctp, *yT, *yg;
    cudaGetSymbolAddress((void**)&xr,   g_xr);
    cudaGetSymbolAddress((void**)&u,    g_u);
    cudaGetSymbolAddress((void**)&uT,   g_uT);
    cudaGetSymbolAddress((void**)&dt,   g_dt);
    cudaGetSymbolAddress((void**)&dtT,  g_dtT);
    cudaGetSymbolAddress((void**)&xdbl, g_xdbl);
    cudaGetSymbolAddress((void**)&wpad, g_wpad);
    cudaGetSymbolAddress((void**)&Btp,  g_Bt);
    cudaGetSymbolAddress((void**)&Ctp,  g_Ct);
    cudaGetSymbolAddress((void**)&yT,   g_yT);
    cudaGetSymbolAddress((void**)&yg,   g_yg);

    // 0) pad x_proj weight to 128 rows (zeros in dead rows)
    pad_w<<<(XPN*DINNER + 255)/256, 256>>>(x_proj_w, wpad);

    // 1) in_proj: xr[8192,4096] = x[8192,1024] @ in_proj_w^T   (tf32 MMA)
    mma_nt<0><<<dim3(2*DINNER/128, MTOK/128), 256>>>(
        MTOK, 2*DINNER, DMODEL, x, DMODEL, in_proj_w, DMODEL, xr, 2*DINNER, nullptr);

    // 2) causal depthwise conv + SiLU -> u (B,L,D)
    conv_silu<<<(MTOK*DINNER)/256, 256>>>(xr, conv_w, conv_b, u);

    // 3) u -> uT (B,D,L)
    transpose_bt<<<dim3(DINNER/32, SEQ/32, BATCH), dim3(32,8)>>>(u, uT);

    // 4) x_dbl[8192,128pad] = u @ wpad^T  (tf32 MMA)
    mma_nt<0><<<dim3(1, MTOK/128), 256>>>(
        MTOK, XPN, DINNER, u, DINNER, wpad, DINNER, xdbl, XPN, nullptr);

    // 5) dt[8192,2048] = softplus(x_dbl[:, :64] @ dt_proj_w^T + b)  (tf32 MMA)
    mma_nt<1><<<dim3(DINNER/128, MTOK/128), 256>>>(
        MTOK, DINNER, DTRANK, xdbl, XPN, dt_proj_w, DTRANK, dt, DINNER, dt_proj_b);

    // 6) dt -> dtT (B,D,L)
    transpose_bt<<<dim3(DINNER/32, SEQ/32, BATCH), dim3(32,8)>>>(dt, dtT);

    // 7) split B/C columns -> (B,16,L)
    split_bc<<<(BATCH*SEQ*DSTATE)/256, 256>>>(xdbl, Btp, Ctp);

    // 8) selective scan -> yT (B,D,L)
    scan_kernel<<<(BATCH*DINNER)/16, 256>>>(uT, dtT, Btp, Ctp, A_log, Dvec, yT);

    // 9) gate with silu(res), transpose back -> yg (B,L,D)
    gate_transpose<<<dim3(SEQ/32, DINNER/32, BATCH), dim3(32,8)>>>(yT, xr, yg);

    // 10) out_proj: out[8192,1024] = yg @ out_proj_w^T  (tf32 MMA)
    mma_nt<0><<<dim3(DMODEL/128, MTOK/128), 256>>>(
        MTOK, DMODEL, DINNER, yg, DINNER, out_proj_w, DINNER, out, DMODEL, nullptr);
}